// round 8
// baseline (speedup 1.0000x reference)
#include <cuda_runtime.h>
#include <cuda_fp16.h>
#include <cstdint>

// Transposed conv (full conv): B=8, H=W=256, CIN=COUT=64, 3x3, fp32 NHWC.
// out[b,p,q,co] = sum_{di,dj,ci} in[b,p-di,q-dj,ci] * ker[ci,co,di,dj]
// mma.sync fp16 implicit GEMM, single product, fp32 accumulate.
// 512 threads (16 warps): warp grid 2(m: 32px) x 8(row), each warp owns
// 32px x 64co of one output row -> 2A+4B ldm4 per 16 mma (0.375 ratio).

#define IH 256
#define IW 256
#define NCH 64
#define OH 258
#define OW 258

// smem layout
#define B_TAP 8192                     // per tap: 64 co rows x 128B (fp16 K-major)
#define SM_B 0
#define SM_A (9 * B_TAP)               // 73728
#define A_SLOT 8704                    // 68 px rows * 128B
#define SM_TOTAL (SM_A + 16 * A_SLOT)  // 212992

#define NPB 33                         // 8-row blocks per strip (264 >= 258)
#define NSTRIP 32                      // 8 b * 4 q-strips of 64
#define NMAIN (NSTRIP * NPB)           // 1056
#define NTPX (8 * OH * 2)              // 4128 tail pixels
#define NTAIL 65
#define NCTA 152
#define NTHR 512

__device__ __forceinline__ uint32_t smem_u32(const void* p) {
    uint32_t a;
    asm("{ .reg .u64 t; cvta.to.shared.u64 t, %1; cvt.u32.u64 %0, t; }" : "=r"(a) : "l"(p));
    return a;
}

__device__ __forceinline__ void ldm4(uint32_t* r, uint32_t a) {
    asm volatile("ldmatrix.sync.aligned.m8n8.x4.shared.b16 {%0,%1,%2,%3}, [%4];"
                 : "=r"(r[0]), "=r"(r[1]), "=r"(r[2]), "=r"(r[3]) : "r"(a));
}

__device__ __forceinline__ void mma16816(float* c, const uint32_t* a,
                                         uint32_t b0, uint32_t b1) {
    asm volatile(
        "mma.sync.aligned.m16n8k16.row.col.f32.f16.f16.f32 "
        "{%0,%1,%2,%3}, {%4,%5,%6,%7}, {%8,%9}, {%0,%1,%2,%3};"
        : "+f"(c[0]), "+f"(c[1]), "+f"(c[2]), "+f"(c[3])
        : "r"(a[0]), "r"(a[1]), "r"(a[2]), "r"(a[3]), "r"(b0), "r"(b1));
}

// convert one input row (fp32 -> fp16) into ring slot r & 15
__device__ __forceinline__ void convert_row(char* smc, int b, int qg0, int r,
                                            const float* __restrict__ gin) {
    char* dst = smc + SM_A + (r & 15) * A_SLOT;
    const float* src = gin + (((size_t)b * IH + r) * IW) * NCH;
    for (int idx = threadIdx.x; idx < 68 * 16; idx += NTHR) {
        int j = idx >> 4, c4 = idx & 15;
        int c = qg0 - 2 + j;
        float4 v = make_float4(0.f, 0.f, 0.f, 0.f);
        if (c >= 0 && c < IW)
            v = __ldg((const float4*)(src + (size_t)c * NCH + c4 * 4));
        __half2 h01 = make_half2(__float2half_rn(v.x), __float2half_rn(v.y));
        __half2 h23 = make_half2(__float2half_rn(v.z), __float2half_rn(v.w));
        uint32_t off = (uint32_t)j * 128 + (uint32_t)c4 * 8;
        uint32_t sw = off ^ ((off >> 3) & 0x70);
        *(uint2*)(dst + sw) = make_uint2(*(uint32_t*)&h01, *(uint32_t*)&h23);
    }
}

__global__ void __launch_bounds__(NTHR, 1)
tconv_mma_kernel(const float* __restrict__ gin, const float* __restrict__ gw,
                 float* __restrict__ gout)
{
    extern __shared__ char smem[];
    const uint32_t sb = smem_u32(smem);
    const int tid = threadIdx.x;
    const int lane = tid & 31;
    const int wid = tid >> 5;
    const int warp_m = wid & 1;          // 32-px group
    const int warp_r = wid >> 1;         // row within 8-row block

    // ---- weight convert: gw[ci][co][tap] -> smem W^T[co][ci] fp16 ----
    for (int e = tid; e < NCH * NCH; e += NTHR) {
        int ci = e >> 6, co = e & 63;
        const float* wp = gw + (size_t)e * 9;
        uint32_t off = (uint32_t)co * 128 + (uint32_t)ci * 2;
        uint32_t sw = off ^ ((off >> 3) & 0x70);
#pragma unroll
        for (int tap = 0; tap < 9; tap++) {
            __half h = __float2half_rn(wp[tap]);
            *(unsigned short*)(smem + SM_B + tap * B_TAP + sw) = __half_as_ushort(h);
        }
    }

    // ldmatrix lane maps
    const int lm = (lane & 7) + ((lane >> 3) & 1) * 8;   // row within 16
    const uint32_t kcl = (uint32_t)((lane >> 4) & 1) * 16;
    const uint32_t bm = (uint32_t)(lm & 7) << 4;         // B swizzle mask (same all tiles)
    uint32_t brow[4];
#pragma unroll
    for (int i = 0; i < 4; i++) brow[i] = (uint32_t)(i * 16 + lm) * 128;

    const int u0 = (int)(((long long)blockIdx.x * NMAIN) / NCTA);
    const int u1 = (int)(((long long)(blockIdx.x + 1) * NMAIN) / NCTA);
    int cur_strip = -1;

    for (int u = u0; u < u1; u++) {
        const int strip = u / NPB;
        const int pb = u - strip * NPB;
        const int p0 = pb * 8;
        const int b = strip >> 2;
        const int qg0 = (strip & 3) * 64;

        __syncthreads();   // prev compute done before ring overwrite
        if (strip != cur_strip) {
            if (p0 - 2 >= 0 && p0 - 2 < IH) convert_row(smem, b, qg0, p0 - 2, gin);
            if (p0 - 1 >= 0 && p0 - 1 < IH) convert_row(smem, b, qg0, p0 - 1, gin);
            cur_strip = strip;
        }
#pragma unroll
        for (int rr = 0; rr < 8; rr++)
            if (p0 + rr < IH) convert_row(smem, b, qg0, p0 + rr, gin);
        __syncthreads();

        // ---- compute: this warp's row pw, 32px x 64co ----
        const int pw = p0 + warp_r;
        float c[2][8][4];
#pragma unroll
        for (int mi = 0; mi < 2; mi++)
#pragma unroll
            for (int ni = 0; ni < 8; ni++)
#pragma unroll
                for (int j = 0; j < 4; j++) c[mi][ni][j] = 0.f;

#pragma unroll
        for (int di = 0; di < 3; di++) {
            const int rp = pw - di;
            if (rp < 0 || rp >= IH) continue;
            const uint32_t aBase = sb + SM_A + (uint32_t)(rp & 15) * A_SLOT;
#pragma unroll
            for (int dj = 0; dj < 3; dj++) {
                const int tap = di * 3 + dj;
                const int row0 = warp_m * 32 + lm + 2 - dj;   // m-tile 0 row
                const uint32_t bb = sb + SM_B + (uint32_t)tap * B_TAP;
#pragma unroll
                for (int s = 0; s < 4; s++) {
                    const uint32_t kx = (uint32_t)s * 32 + kcl;
                    uint32_t Bf[4][4];
#pragma unroll
                    for (int i = 0; i < 4; i++)
                        ldm4(Bf[i], bb + brow[i] + (kx ^ bm));
                    uint32_t A0[4], A1[4];
                    {
                        const uint32_t r0 = (uint32_t)row0;
                        ldm4(A0, aBase + r0 * 128 + (kx ^ ((r0 & 7) << 4)));
                        const uint32_t r1 = (uint32_t)(row0 + 16);
                        ldm4(A1, aBase + r1 * 128 + (kx ^ ((r1 & 7) << 4)));
                    }
#pragma unroll
                    for (int i = 0; i < 4; i++) {
                        mma16816(c[0][i * 2 + 0], A0, Bf[i][0], Bf[i][2]);
                        mma16816(c[0][i * 2 + 1], A0, Bf[i][1], Bf[i][3]);
                        mma16816(c[1][i * 2 + 0], A1, Bf[i][0], Bf[i][2]);
                        mma16816(c[1][i * 2 + 1], A1, Bf[i][1], Bf[i][3]);
                    }
                }
            }
        }

        // ---- store this warp's row ----
        if (pw < OH) {
            float* orow = gout + (((size_t)b * OH + pw) * OW) * NCH;
#pragma unroll
            for (int mi = 0; mi < 2; mi++) {
                const int q = qg0 + warp_m * 32 + mi * 16 + (lane >> 2);
#pragma unroll
                for (int ni = 0; ni < 8; ni++) {
                    const int co = ni * 8 + (lane & 3) * 2;
                    *(float2*)(orow + (size_t)q * NCH + co) =
                        make_float2(c[mi][ni][0], c[mi][ni][1]);
                    *(float2*)(orow + (size_t)(q + 8) * NCH + co) =
                        make_float2(c[mi][ni][2], c[mi][ni][3]);
                }
            }
        }
    }

    // ================= tail units: q in {256,257}, 64 px per unit ============
    if (blockIdx.x < NTAIL) {
        const int g0 = blockIdx.x * 64;
        // tail warp decode: warps 0..7 cover 64px x 64co (16px x 32co each)
        const int tm = wid & 3;
        const int tn = (wid >> 2) & 1;
        const bool tact = (wid < 8);

        const int tnl0 = tn * 32 + lm;
        const int tnl1 = tnl0 + 16;
        const uint32_t tbrow0 = (uint32_t)tnl0 * 128, tbm0 = (uint32_t)(tnl0 & 7) << 4;
        const uint32_t tbrow1 = (uint32_t)tnl1 * 128, tbm1 = (uint32_t)(tnl1 & 7) << 4;
        const int rowi = tm * 16 + lm;
        const uint32_t arow = (uint32_t)rowi * 128;
        const uint32_t am = (uint32_t)(rowi & 7) << 4;

        float ct[4][4];
#pragma unroll
        for (int i = 0; i < 4; i++)
#pragma unroll
            for (int j = 0; j < 4; j++) ct[i][j] = 0.f;

        for (int tap = 0; tap < 9; tap++) {
            const int di = tap / 3, dj = tap % 3;
            __syncthreads();   // prev tap's mma reads done
            for (int idx = tid; idx < 64 * 16; idx += NTHR) {
                int m = idx >> 4, c4 = idx & 15;
                int g = g0 + m;
                int bb_ = g / (OH * 2);
                int rem = g - bb_ * (OH * 2);
                int p = rem >> 1;
                int qq = 256 + (rem & 1);
                int r = p - di, cc = qq - dj;
                float4 v = make_float4(0.f, 0.f, 0.f, 0.f);
                if (g < NTPX && r >= 0 && r < IH && cc < IW)
                    v = __ldg((const float4*)(gin +
                        ((((size_t)bb_ * IH + r) * IW + cc) * NCH) + c4 * 4));
                __half2 h01 = make_half2(__float2half_rn(v.x), __float2half_rn(v.y));
                __half2 h23 = make_half2(__float2half_rn(v.z), __float2half_rn(v.w));
                uint32_t off = (uint32_t)m * 128 + (uint32_t)c4 * 8;
                uint32_t sw = off ^ ((off >> 3) & 0x70);
                *(uint2*)(smem + SM_A + sw) = make_uint2(*(uint32_t*)&h01, *(uint32_t*)&h23);
            }
            __syncthreads();

            if (tact) {
                const uint32_t bb = sb + SM_B + (uint32_t)tap * B_TAP;
#pragma unroll
                for (int s = 0; s < 4; s++) {
                    const uint32_t kx = (uint32_t)s * 32 + kcl;
                    uint32_t B0[4], B1[4], A[4];
                    ldm4(B0, bb + tbrow0 + (kx ^ tbm0));
                    ldm4(B1, bb + tbrow1 + (kx ^ tbm1));
                    ldm4(A, sb + SM_A + arow + (kx ^ am));
                    mma16816(ct[0], A, B0[0], B0[2]);
                    mma16816(ct[1], A, B0[1], B0[3]);
                    mma16816(ct[2], A, B1[0], B1[2]);
                    mma16816(ct[3], A, B1[1], B1[3]);
                }
            }
        }

        if (tact) {
            const int m0 = tm * 16 + (lane >> 2);
#pragma unroll
            for (int half = 0; half < 2; half++) {
                const int g = g0 + m0 + half * 8;
                if (g < NTPX) {
                    const int bb_ = g / (OH * 2);
                    const int rem = g - bb_ * (OH * 2);
                    const int p = rem >> 1;
                    const int qq = 256 + (rem & 1);
                    float* orow = gout + (((size_t)bb_ * OH + p) * OW + qq) * NCH;
#pragma unroll
                    for (int nt = 0; nt < 4; nt++) {
                        const int co = tn * 32 + nt * 8 + (lane & 3) * 2;
                        *(float2*)(orow + co) =
                            make_float2(ct[nt][half * 2], ct[nt][half * 2 + 1]);
                    }
                }
            }
        }
    }
}

extern "C" void kernel_launch(void* const* d_in, const int* in_sizes, int n_in,
                              void* d_out, int out_size)
{
    const float* gin = (const float*)d_in[0]; // [8,256,256,64]
    const float* gw  = (const float*)d_in[1]; // [64,64,3,3]
    float* gout = (float*)d_out;              // [8,258,258,64]

    cudaFuncSetAttribute(tconv_mma_kernel,
                         cudaFuncAttributeMaxDynamicSharedMemorySize, SM_TOTAL);
    tconv_mma_kernel<<<NCTA, NTHR, SM_TOTAL>>>(gin, gw, gout);
}